// round 2
// baseline (speedup 1.0000x reference)
#include <cuda_runtime.h>
#include <math.h>

#define N_NODES 100000
#define N_EDGES 3200000
#define F_IN 25
#define F_HID 16
#define F_OUT 2

// Scratch (allocation-free rule: __device__ globals)
__device__ float g_deg[N_NODES];
__device__ float g_dinv[N_NODES];
__device__ float g_hs1[N_NODES * F_HID];   // (x@W1) * dinv[i], pre-scaled
__device__ float g_acc1[N_NODES * F_HID];  // edge-scattered sums
__device__ float g_hs2[N_NODES * F_OUT];   // (relu(layer1)@W2) * dinv[i]
__device__ float g_acc2[N_NODES * F_OUT];
__device__ int   g_is64;                   // 1 if edge_index is int64, 0 if int32

// ---------------------------------------------------------------------------
// Detect edge_index dtype: if int64, high 32-bit words are all zero.
__global__ void k_detect(const unsigned int* __restrict__ ei_w) {
    // single block; check 2048 odd words
    __shared__ int nonzero;
    if (threadIdx.x == 0) nonzero = 0;
    __syncthreads();
    for (int i = threadIdx.x; i < 2048; i += blockDim.x) {
        if (ei_w[2 * i + 1] != 0u) atomicOr(&nonzero, 1);
    }
    __syncthreads();
    if (threadIdx.x == 0) g_is64 = (nonzero == 0) ? 1 : 0;
}

__device__ __forceinline__ int load_row(const void* ei, int e) {
    if (g_is64) return (int)((const long long*)ei)[e];
    return ((const int*)ei)[e];
}
__device__ __forceinline__ int load_col(const void* ei, int e) {
    if (g_is64) return (int)((const long long*)ei)[N_EDGES + e];
    return ((const int*)ei)[N_EDGES + e];
}

// ---------------------------------------------------------------------------
__global__ void k_zero() {
    int stride = gridDim.x * blockDim.x;
    int tid = blockIdx.x * blockDim.x + threadIdx.x;
    for (int i = tid; i < N_NODES * F_HID; i += stride) g_acc1[i] = 0.0f;
    for (int i = tid; i < N_NODES * F_OUT; i += stride) g_acc2[i] = 0.0f;
    for (int i = tid; i < N_NODES; i += stride) g_deg[i] = 0.0f;
}

// Degree: count incoming edges per target node (self-loop added in k_dinv).
__global__ void k_degree(const void* __restrict__ ei) {
    int e = blockIdx.x * blockDim.x + threadIdx.x;
    if (e >= N_EDGES) return;
    int c = load_col(ei, e);
    atomicAdd(&g_deg[c], 1.0f);
}

__global__ void k_dinv() {
    int i = blockIdx.x * blockDim.x + threadIdx.x;
    if (i >= N_NODES) return;
    g_dinv[i] = rsqrtf(g_deg[i] + 1.0f);  // +1 self-loop; deg>=1 always
}

// Layer-1 transform: hs1[i] = (x[i] @ W1) * dinv[i]
__global__ void k_xform1(const float* __restrict__ x, const float* __restrict__ W1) {
    __shared__ float sW1[F_IN * F_HID];
    for (int i = threadIdx.x; i < F_IN * F_HID; i += blockDim.x)
        sW1[i] = W1[i];
    __syncthreads();

    int i = blockIdx.x * blockDim.x + threadIdx.x;
    if (i >= N_NODES) return;

    float xi[F_IN];
#pragma unroll
    for (int k = 0; k < F_IN; k++) xi[k] = x[i * F_IN + k];

    float acc[F_HID];
#pragma unroll
    for (int f = 0; f < F_HID; f++) acc[f] = 0.0f;
#pragma unroll
    for (int k = 0; k < F_IN; k++) {
        float xv = xi[k];
#pragma unroll
        for (int f = 0; f < F_HID; f++) acc[f] += xv * sW1[k * F_HID + f];
    }

    float di = g_dinv[i];
    float4* out = (float4*)&g_hs1[i * F_HID];
#pragma unroll
    for (int q = 0; q < 4; q++) {
        float4 v;
        v.x = acc[q * 4 + 0] * di;
        v.y = acc[q * 4 + 1] * di;
        v.z = acc[q * 4 + 2] * di;
        v.w = acc[q * 4 + 3] * di;
        out[q] = v;
    }
}

// Layer-1 edge scatter: acc1[col] += hs1[row]
__global__ void k_scatter1(const void* __restrict__ ei) {
    int e = blockIdx.x * blockDim.x + threadIdx.x;
    if (e >= N_EDGES) return;
    int r = load_row(ei, e);
    int c = load_col(ei, e);
    const float4* src = (const float4*)&g_hs1[r * F_HID];
    float* dst = &g_acc1[c * F_HID];
#pragma unroll
    for (int q = 0; q < 4; q++) {
        float4 v = src[q];
        atomicAdd(dst + q * 4 + 0, v.x);
        atomicAdd(dst + q * 4 + 1, v.y);
        atomicAdd(dst + q * 4 + 2, v.z);
        atomicAdd(dst + q * 4 + 3, v.w);
    }
}

// Finalize layer 1 (+ self loop, bias, relu) then transform 2:
// hs2[i] = (relu((acc1[i]+hs1[i])*dinv[i] + b1) @ W2) * dinv[i]
__global__ void k_fin1_xform2(const float* __restrict__ b1,
                              const float* __restrict__ W2) {
    __shared__ float sW2[F_HID * F_OUT];
    __shared__ float sb1[F_HID];
    if (threadIdx.x < F_HID * F_OUT) sW2[threadIdx.x] = W2[threadIdx.x];
    if (threadIdx.x < F_HID) sb1[threadIdx.x] = b1[threadIdx.x];
    __syncthreads();

    int i = blockIdx.x * blockDim.x + threadIdx.x;
    if (i >= N_NODES) return;

    float di = g_dinv[i];
    const float4* a = (const float4*)&g_acc1[i * F_HID];
    const float4* h = (const float4*)&g_hs1[i * F_HID];
    float v[F_HID];
#pragma unroll
    for (int q = 0; q < 4; q++) {
        float4 av = a[q];
        float4 hv = h[q];
        v[q * 4 + 0] = (av.x + hv.x) * di + sb1[q * 4 + 0];
        v[q * 4 + 1] = (av.y + hv.y) * di + sb1[q * 4 + 1];
        v[q * 4 + 2] = (av.z + hv.z) * di + sb1[q * 4 + 2];
        v[q * 4 + 3] = (av.w + hv.w) * di + sb1[q * 4 + 3];
    }
#pragma unroll
    for (int f = 0; f < F_HID; f++) v[f] = fmaxf(v[f], 0.0f);

    float o0 = 0.0f, o1 = 0.0f;
#pragma unroll
    for (int f = 0; f < F_HID; f++) {
        o0 += v[f] * sW2[f * F_OUT + 0];
        o1 += v[f] * sW2[f * F_OUT + 1];
    }
    g_hs2[i * F_OUT + 0] = o0 * di;
    g_hs2[i * F_OUT + 1] = o1 * di;
}

// Layer-2 edge scatter: acc2[col] += hs2[row]
__global__ void k_scatter2(const void* __restrict__ ei) {
    int e = blockIdx.x * blockDim.x + threadIdx.x;
    if (e >= N_EDGES) return;
    int r = load_row(ei, e);
    int c = load_col(ei, e);
    float2 v = *(const float2*)&g_hs2[r * F_OUT];
    atomicAdd(&g_acc2[c * F_OUT + 0], v.x);
    atomicAdd(&g_acc2[c * F_OUT + 1], v.y);
}

// Finalize layer 2 + log_softmax
__global__ void k_fin2(const float* __restrict__ b2, float* __restrict__ out) {
    int i = blockIdx.x * blockDim.x + threadIdx.x;
    if (i >= N_NODES) return;
    float di = g_dinv[i];
    float b20 = b2[0], b21 = b2[1];
    float o0 = (g_acc2[i * F_OUT + 0] + g_hs2[i * F_OUT + 0]) * di + b20;
    float o1 = (g_acc2[i * F_OUT + 1] + g_hs2[i * F_OUT + 1]) * di + b21;
    float m = fmaxf(o0, o1);
    float lse = m + logf(expf(o0 - m) + expf(o1 - m));
    float2 r;
    r.x = o0 - lse;
    r.y = o1 - lse;
    *(float2*)&out[i * F_OUT] = r;
}

// ---------------------------------------------------------------------------
extern "C" void kernel_launch(void* const* d_in, const int* in_sizes, int n_in,
                              void* d_out, int out_size) {
    const float* x = (const float*)d_in[0];
    const void* ei = d_in[1];
    const float* W1 = (const float*)d_in[2];
    const float* b1 = (const float*)d_in[3];
    const float* W2 = (const float*)d_in[4];
    const float* b2 = (const float*)d_in[5];
    float* out = (float*)d_out;

    const int TB = 256;
    int nblk_node = (N_NODES + TB - 1) / TB;
    int nblk_edge = (N_EDGES + TB - 1) / TB;

    k_detect<<<1, 256>>>((const unsigned int*)ei);
    k_zero<<<592, TB>>>();  // grid-stride
    k_degree<<<nblk_edge, TB>>>(ei);
    k_dinv<<<nblk_node, TB>>>();
    k_xform1<<<nblk_node, TB>>>(x, W1);
    k_scatter1<<<nblk_edge, TB>>>(ei);
    k_fin1_xform2<<<nblk_node, TB>>>(b1, W2);
    k_scatter2<<<nblk_edge, TB>>>(ei);
    k_fin2<<<nblk_node, TB>>>(b2, out);
}

// round 3
// speedup vs baseline: 2.1383x; 2.1383x over previous
#include <cuda_runtime.h>
#include <math.h>

#define N_NODES 100000
#define N_EDGES 3200000
#define F_IN 25
#define F_HID 16
#define F_OUT 2

// Scratch (allocation-free rule: __device__ globals)
__device__ float g_deg[N_NODES];
__device__ float g_dinv[N_NODES];
__device__ float g_hs1[N_NODES * F_HID];   // (x@W1) * dinv[i], pre-scaled
__device__ float g_acc1[N_NODES * F_HID];  // edge-scattered sums
__device__ float g_hs2[N_NODES * F_OUT];   // (relu(layer1)@W2) * dinv[i]
__device__ float g_acc2[N_NODES * F_OUT];
__device__ int   g_is64;                   // 1 if edge_index is int64, 0 if int32

// ---------------------------------------------------------------------------
__device__ __forceinline__ void red_add_v4(float* p, float a, float b, float c, float d) {
    asm volatile("red.global.add.v4.f32 [%0], {%1, %2, %3, %4};"
                 :: "l"(p), "f"(a), "f"(b), "f"(c), "f"(d) : "memory");
}
__device__ __forceinline__ void red_add_v2(float* p, float a, float b) {
    asm volatile("red.global.add.v2.f32 [%0], {%1, %2};"
                 :: "l"(p), "f"(a), "f"(b) : "memory");
}

// Detect edge_index dtype: if int64, high 32-bit words are all zero.
__global__ void k_detect(const unsigned int* __restrict__ ei_w) {
    __shared__ int nonzero;
    if (threadIdx.x == 0) nonzero = 0;
    __syncthreads();
    for (int i = threadIdx.x; i < 2048; i += blockDim.x) {
        if (ei_w[2 * i + 1] != 0u) atomicOr(&nonzero, 1);
    }
    __syncthreads();
    if (threadIdx.x == 0) g_is64 = (nonzero == 0) ? 1 : 0;
}

__device__ __forceinline__ int load_row(const void* ei, int e) {
    if (g_is64) return (int)((const long long*)ei)[e];
    return ((const int*)ei)[e];
}
__device__ __forceinline__ int load_col(const void* ei, int e) {
    if (g_is64) return (int)((const long long*)ei)[N_EDGES + e];
    return ((const int*)ei)[N_EDGES + e];
}

// ---------------------------------------------------------------------------
__global__ void k_zero() {
    int stride = gridDim.x * blockDim.x;
    int tid = blockIdx.x * blockDim.x + threadIdx.x;
    for (int i = tid; i < N_NODES * F_HID; i += stride) g_acc1[i] = 0.0f;
    for (int i = tid; i < N_NODES * F_OUT; i += stride) g_acc2[i] = 0.0f;
    for (int i = tid; i < N_NODES; i += stride) g_deg[i] = 0.0f;
}

// Degree: count incoming edges per target node (self-loop added later).
__global__ void k_degree(const void* __restrict__ ei) {
    int e = blockIdx.x * blockDim.x + threadIdx.x;
    if (e >= N_EDGES) return;
    int c = load_col(ei, e);
    atomicAdd(&g_deg[c], 1.0f);  // no return use -> REDG
}

// Layer-1 transform fused with dinv: hs1[i] = (x[i] @ W1) * dinv[i]
__global__ void k_xform1(const float* __restrict__ x, const float* __restrict__ W1) {
    __shared__ float sW1[F_IN * F_HID];
    for (int i = threadIdx.x; i < F_IN * F_HID; i += blockDim.x)
        sW1[i] = W1[i];
    __syncthreads();

    int i = blockIdx.x * blockDim.x + threadIdx.x;
    if (i >= N_NODES) return;

    float di = rsqrtf(g_deg[i] + 1.0f);  // +1 self-loop
    g_dinv[i] = di;

    float xi[F_IN];
#pragma unroll
    for (int k = 0; k < F_IN; k++) xi[k] = x[i * F_IN + k];

    float acc[F_HID];
#pragma unroll
    for (int f = 0; f < F_HID; f++) acc[f] = 0.0f;
#pragma unroll
    for (int k = 0; k < F_IN; k++) {
        float xv = xi[k];
#pragma unroll
        for (int f = 0; f < F_HID; f++) acc[f] += xv * sW1[k * F_HID + f];
    }

    float4* out = (float4*)&g_hs1[i * F_HID];
#pragma unroll
    for (int q = 0; q < 4; q++) {
        float4 v;
        v.x = acc[q * 4 + 0] * di;
        v.y = acc[q * 4 + 1] * di;
        v.z = acc[q * 4 + 2] * di;
        v.w = acc[q * 4 + 3] * di;
        out[q] = v;
    }
}

// Layer-1 edge scatter: acc1[col] += hs1[row]  (vector reductions)
__global__ void k_scatter1(const void* __restrict__ ei) {
    int e = blockIdx.x * blockDim.x + threadIdx.x;
    if (e >= N_EDGES) return;
    int r = load_row(ei, e);
    int c = load_col(ei, e);
    const float4* src = (const float4*)&g_hs1[r * F_HID];
    float* dst = &g_acc1[c * F_HID];
#pragma unroll
    for (int q = 0; q < 4; q++) {
        float4 v = __ldg(src + q);
        red_add_v4(dst + q * 4, v.x, v.y, v.z, v.w);
    }
}

// Finalize layer 1 (+ self loop, bias, relu) then transform 2:
// hs2[i] = (relu((acc1[i]+hs1[i])*dinv[i] + b1) @ W2) * dinv[i]
__global__ void k_fin1_xform2(const float* __restrict__ b1,
                              const float* __restrict__ W2) {
    __shared__ float sW2[F_HID * F_OUT];
    __shared__ float sb1[F_HID];
    if (threadIdx.x < F_HID * F_OUT) sW2[threadIdx.x] = W2[threadIdx.x];
    if (threadIdx.x < F_HID) sb1[threadIdx.x] = b1[threadIdx.x];
    __syncthreads();

    int i = blockIdx.x * blockDim.x + threadIdx.x;
    if (i >= N_NODES) return;

    float di = g_dinv[i];
    const float4* a = (const float4*)&g_acc1[i * F_HID];
    const float4* h = (const float4*)&g_hs1[i * F_HID];
    float v[F_HID];
#pragma unroll
    for (int q = 0; q < 4; q++) {
        float4 av = a[q];
        float4 hv = h[q];
        v[q * 4 + 0] = (av.x + hv.x) * di + sb1[q * 4 + 0];
        v[q * 4 + 1] = (av.y + hv.y) * di + sb1[q * 4 + 1];
        v[q * 4 + 2] = (av.z + hv.z) * di + sb1[q * 4 + 2];
        v[q * 4 + 3] = (av.w + hv.w) * di + sb1[q * 4 + 3];
    }
#pragma unroll
    for (int f = 0; f < F_HID; f++) v[f] = fmaxf(v[f], 0.0f);

    float o0 = 0.0f, o1 = 0.0f;
#pragma unroll
    for (int f = 0; f < F_HID; f++) {
        o0 += v[f] * sW2[f * F_OUT + 0];
        o1 += v[f] * sW2[f * F_OUT + 1];
    }
    g_hs2[i * F_OUT + 0] = o0 * di;
    g_hs2[i * F_OUT + 1] = o1 * di;
}

// Layer-2 edge scatter: acc2[col] += hs2[row]  (v2 reduction)
__global__ void k_scatter2(const void* __restrict__ ei) {
    int e = blockIdx.x * blockDim.x + threadIdx.x;
    if (e >= N_EDGES) return;
    int r = load_row(ei, e);
    int c = load_col(ei, e);
    float2 v = __ldg((const float2*)&g_hs2[r * F_OUT]);
    red_add_v2(&g_acc2[c * F_OUT], v.x, v.y);
}

// Finalize layer 2 + log_softmax
__global__ void k_fin2(const float* __restrict__ b2, float* __restrict__ out) {
    int i = blockIdx.x * blockDim.x + threadIdx.x;
    if (i >= N_NODES) return;
    float di = g_dinv[i];
    float b20 = b2[0], b21 = b2[1];
    float o0 = (g_acc2[i * F_OUT + 0] + g_hs2[i * F_OUT + 0]) * di + b20;
    float o1 = (g_acc2[i * F_OUT + 1] + g_hs2[i * F_OUT + 1]) * di + b21;
    float m = fmaxf(o0, o1);
    float lse = m + logf(expf(o0 - m) + expf(o1 - m));
    float2 r;
    r.x = o0 - lse;
    r.y = o1 - lse;
    *(float2*)&out[i * F_OUT] = r;
}

// ---------------------------------------------------------------------------
extern "C" void kernel_launch(void* const* d_in, const int* in_sizes, int n_in,
                              void* d_out, int out_size) {
    const float* x = (const float*)d_in[0];
    const void* ei = d_in[1];
    const float* W1 = (const float*)d_in[2];
    const float* b1 = (const float*)d_in[3];
    const float* W2 = (const float*)d_in[4];
    const float* b2 = (const float*)d_in[5];
    float* out = (float*)d_out;

    const int TB = 256;
    int nblk_node = (N_NODES + TB - 1) / TB;
    int nblk_edge = (N_EDGES + TB - 1) / TB;

    k_detect<<<1, 256>>>((const unsigned int*)ei);
    k_zero<<<592, TB>>>();
    k_degree<<<nblk_edge, TB>>>(ei);
    k_xform1<<<nblk_node, TB>>>(x, W1);
    k_scatter1<<<nblk_edge, TB>>>(ei);
    k_fin1_xform2<<<nblk_node, TB>>>(b1, W2);
    k_scatter2<<<nblk_edge, TB>>>(ei);
    k_fin2<<<nblk_node, TB>>>(b2, out);
}